// round 3
// baseline (speedup 1.0000x reference)
#include <cuda_runtime.h>

// MySoftBCELoss: per-row soft BCE with argmax-label branch, mean-reduced.
// B = 1048576 rows, C = 32 cols (one warp lane per class). Streaming, HBM-bound.
// Single kernel: grid-wide sum finished by the last-arriving CTA (fence
// reduction, fixed-order sum -> deterministic), saving the 2nd launch.
// Grid = 608 CTAs = one resident wave on GB300 (152 SM x 4 CTA/SM @ 256 thr).

static constexpr int C       = 32;
static constexpr int BLOCKS  = 608;
static constexpr int THREADS = 256;
static constexpr int WPB     = THREADS / 32;

__device__ float        g_partial[BLOCKS];
__device__ unsigned int g_count = 0;   // reset by last block each run -> graph-replay safe

__global__ __launch_bounds__(THREADS) void bce_fused(const float* __restrict__ logits,
                                                     const float* __restrict__ target,
                                                     float* __restrict__ out,
                                                     int nrows) {
    // log(1e-7) and log(1 - 1e-7): clamping the logs == clamping pred (log monotone).
    constexpr float LOGEPS   = -16.118095651f;
    constexpr float LOG1MEPS = -1.0000001192e-7f;

    const int lane   = threadIdx.x & 31;
    const int gwarp  = blockIdx.x * WPB + (threadIdx.x >> 5);
    const int nwarps = BLOCKS * WPB;

    float acc = 0.0f;

    #pragma unroll 4
    for (int row = gwarp; row < nrows; row += nwarps) {
        const int idx = row * C + lane;          // coalesced: warp covers one 128B row
        const float x = __ldcs(&logits[idx]);    // touched once: streaming hint
        const float t = __ldcs(&target[idx]);

        // pred = clamp(sigmoid(x), eps, 1-eps)
        // log(pred) = -log(1+e^{-x}); log(1-pred) = -x - log(1+e^{-x})
        // 1 EX2 + 1 LG2 per element — MUFU-minimal (SIMT: per-warp cost is the
        // same whether 2 or 32 lanes need the result, so no lazy-eval win).
        const float xc = fmaxf(x, -80.0f);       // exp finite; clamp region lies
                                                 // strictly inside the eps clamp
        const float e  = __expf(-xc);
        const float ld = __logf(1.0f + e);
        const float logp   = fminf(fmaxf(-ld,      LOGEPS), LOG1MEPS);
        const float log1mp = fminf(fmaxf(-xc - ld, LOGEPS), LOG1MEPS);

        // argmax over the row, first-index tie-break (matches jnp.argmax).
        // target in [0,1) => uint bit order == float order.
        const unsigned tb  = __float_as_uint(t);
        const unsigned mb  = __reduce_max_sync(0xffffffffu, tb);
        const unsigned bal = __ballot_sync(0xffffffffu, tb == mb);
        const int mi = __ffs(bal) - 1;           // warp-uniform -> no divergence

        if (mi == 0) {
            // loss0 = mean_c( t*logp + (1-t)*log1mp ): each lane adds its share.
            acc += (t * logp + (1.0f - t) * log1mp) * (1.0f / 32.0f);
        } else {
            // loss1 = t[mi]*logp[mi] + 1.0*log1mp[0]: owning lanes add directly.
            if (lane == mi) acc += t * logp;
            if (lane == 0)  acc += log1mp;
        }
    }

    // One warp reduction per warp (not per row), then fixed-order block sum.
    #pragma unroll
    for (int o = 16; o; o >>= 1) acc += __shfl_xor_sync(0xffffffffu, acc, o);

    __shared__ float sm[WPB];
    __shared__ bool  amLast;
    if (lane == 0) sm[threadIdx.x >> 5] = acc;
    __syncthreads();

    if (threadIdx.x == 0) {
        float s = 0.0f;
        #pragma unroll
        for (int i = 0; i < WPB; i++) s += sm[i];
        g_partial[blockIdx.x] = s;               // fixed slot per block
        __threadfence();                         // publish partial before ticket
        const unsigned rank = atomicAdd(&g_count, 1u);
        amLast = (rank == BLOCKS - 1);
    }
    __syncthreads();

    // Last-arriving CTA: sum all partials in FIXED index order -> deterministic
    // result independent of block completion order.
    if (amLast) {
        float s = 0.0f;
        for (int i = threadIdx.x; i < BLOCKS; i += THREADS) s += g_partial[i];
        #pragma unroll
        for (int o = 16; o; o >>= 1) s += __shfl_xor_sync(0xffffffffu, s, o);
        __shared__ float sm2[WPB];
        if (lane == 0) sm2[threadIdx.x >> 5] = s;
        __syncthreads();
        if (threadIdx.x == 0) {
            float tot = 0.0f;
            #pragma unroll
            for (int i = 0; i < WPB; i++) tot += sm2[i];
            out[0] = -tot / (float)nrows;
            g_count = 0;                         // reset for next graph replay
        }
    }
}

extern "C" void kernel_launch(void* const* d_in, const int* in_sizes, int n_in,
                              void* d_out, int out_size) {
    const float* logits = (const float*)d_in[0];
    const float* target = (const float*)d_in[1];
    const int nrows = in_sizes[0] / C;
    bce_fused<<<BLOCKS, THREADS>>>(logits, target, (float*)d_out, nrows);
}

// round 10
// speedup vs baseline: 1.3755x; 1.3755x over previous
#include <cuda_runtime.h>

// MySoftBCELoss: per-row soft BCE with argmax-label branch, mean-reduced.
// B = 1048576 rows, C = 32 cols, fp32. 256 MB streamed -> HBM-bound target.
//
// R3 ncu (scalar version): DRAM 42%, occ 49%, issue 40% => latency-bound.
// Design: float4 (LDG.128) loads -- one warp-iter covers 4 rows (512B per
// tensor); 8-lane segmented argmax; branchless label select. Grid = 2048 CTAs
// so stride (2^19) divides n4 (2^23): every thread runs exactly 16 counted
// iterations -> no per-iter bound compare, ptxas front-batches the unrolled
// LDG.128s (8 in flight/thread ~ 32KB/SM, covers ~577cyc DRAM latency).

static constexpr int BLOCKS  = 2048;
static constexpr int THREADS = 256;
static constexpr int WPB     = THREADS / 32;

__device__ float        g_partial[BLOCKS];
__device__ unsigned int g_count = 0;   // reset by last block -> graph-replay safe

__global__ __launch_bounds__(THREADS) void bce_fused(const float4* __restrict__ lg4,
                                                     const float4* __restrict__ tg4,
                                                     float* __restrict__ out,
                                                     int nrows) {
    // log(1e-7), log(1-1e-7): clamping logs == clamping pred (log monotone).
    constexpr float LOGEPS   = -16.118095651f;
    constexpr float LOG1MEPS = -1.0000001192e-7f;

    const int lane    = threadIdx.x & 31;
    const int segbase = lane & 24;                  // (lane/8)*8: segment leader lane
    const unsigned segmask = 0xFFu << segbase;      // 8 lanes == one 32-col row

    const int n4     = nrows * 8;                   // float4s per tensor (32 cols / 4)
    const int stride = BLOCKS * THREADS;
    const int base   = blockIdx.x * THREADS + threadIdx.x;
    const int iters  = n4 / stride;                 // 16 for the bench shape (exact)

    float acc = 0.0f;

    #pragma unroll 4
    for (int k = 0; k < iters; k++) {
        const int i = base + k * stride;
        // Warp covers 128 consecutive float4s = 4 full rows; segment s owns row s.
        const float4 xv = __ldcs(&lg4[i]);
        const float4 tv = __ldcs(&tg4[i]);
        const float xs[4] = {xv.x, xv.y, xv.z, xv.w};
        const float ts[4] = {tv.x, tv.y, tv.z, tv.w};

        float lp[4], lmp[4], pr[4];
        unsigned tb[4];
        #pragma unroll
        for (int j = 0; j < 4; j++) {
            // log(pred) = -log(1+e^{-x}); log(1-pred) = -x - log(1+e^{-x})
            // 1 EX2 + 1 LG2 per element (MUFU-minimal).
            const float xc = fmaxf(xs[j], -80.0f);  // exp finite; inside eps-clamp region
            const float e  = __expf(-xc);
            const float ld = __logf(1.0f + e);
            lp[j]  = fminf(fmaxf(-ld,      LOGEPS), LOG1MEPS);
            lmp[j] = fminf(fmaxf(-xc - ld, LOGEPS), LOG1MEPS);
            pr[j]  = ts[j] * lp[j];
            tb[j]  = __float_as_uint(ts[j]);        // t in [0,1): uint order == float order
        }

        // Segmented argmax over the 32 columns of this lane's row.
        const unsigned lm     = max(max(tb[0], tb[1]), max(tb[2], tb[3]));
        const unsigned segmax = __reduce_max_sync(segmask, lm);
        const unsigned ball   = __ballot_sync(0xffffffffu, lm == segmax) & segmask;
        const int firstlane   = __ffs(ball) - 1;    // first (lowest-column) max lane
        // argmax == 0 iff column 0 (lane segbase, elem 0) equals the max.
        const unsigned b0ball = __ballot_sync(0xffffffffu, tb[0] == segmax);
        const bool label0     = (b0ball >> segbase) & 1u;

        // loss0 share: this lane's 4 columns of mean_c(t*logp + (1-t)*log1mp).
        float bce = 0.0f;
        #pragma unroll
        for (int j = 0; j < 4; j++) bce += pr[j] + (1.0f - ts[j]) * lmp[j];

        // loss1 pieces: first-max lane adds t[lab]*logp[lab] (first-j tie-break
        // inside the lane preserves first-index semantics); segment leader adds
        // log1mp[col 0].
        const float plab = (tb[0] == segmax) ? pr[0]
                         : (tb[1] == segmax) ? pr[1]
                         : (tb[2] == segmax) ? pr[2] : pr[3];
        const float s1 = ((lane == firstlane) ? plab : 0.0f)
                       + ((lane == segbase)   ? lmp[0] : 0.0f);

        acc += label0 ? (bce * (1.0f / 32.0f)) : s1;   // FSEL, no branch
    }

    // Shape-robust tail (no-op for the bench shape: 2^23 % 2^19 == 0).
    {
        const int i = base + iters * stride;
        if (i < n4) {
            const float4 xv = __ldcs(&lg4[i]);
            const float4 tv = __ldcs(&tg4[i]);
            const float xs[4] = {xv.x, xv.y, xv.z, xv.w};
            const float ts[4] = {tv.x, tv.y, tv.z, tv.w};
            float lp[4], lmp[4], pr[4];
            unsigned tb[4];
            #pragma unroll
            for (int j = 0; j < 4; j++) {
                const float xc = fmaxf(xs[j], -80.0f);
                const float e  = __expf(-xc);
                const float ld = __logf(1.0f + e);
                lp[j]  = fminf(fmaxf(-ld,      LOGEPS), LOG1MEPS);
                lmp[j] = fminf(fmaxf(-xc - ld, LOGEPS), LOG1MEPS);
                pr[j]  = ts[j] * lp[j];
                tb[j]  = __float_as_uint(ts[j]);
            }
            const unsigned lm     = max(max(tb[0], tb[1]), max(tb[2], tb[3]));
            const unsigned segmax = __reduce_max_sync(segmask, lm);
            const unsigned ball   = __ballot_sync(0xffffffffu, lm == segmax) & segmask;
            const int firstlane   = __ffs(ball) - 1;
            const unsigned b0ball = __ballot_sync(0xffffffffu, tb[0] == segmax);
            const bool label0     = (b0ball >> segbase) & 1u;
            float bce = 0.0f;
            #pragma unroll
            for (int j = 0; j < 4; j++) bce += pr[j] + (1.0f - ts[j]) * lmp[j];
            const float plab = (tb[0] == segmax) ? pr[0]
                             : (tb[1] == segmax) ? pr[1]
                             : (tb[2] == segmax) ? pr[2] : pr[3];
            const float s1 = ((lane == firstlane) ? plab : 0.0f)
                           + ((lane == segbase)   ? lmp[0] : 0.0f);
            acc += label0 ? (bce * (1.0f / 32.0f)) : s1;
        }
    }

    // One warp reduction per warp, then fixed-order block sum.
    #pragma unroll
    for (int o = 16; o; o >>= 1) acc += __shfl_xor_sync(0xffffffffu, acc, o);

    __shared__ float sm[WPB];
    __shared__ bool  amLast;
    if (lane == 0) sm[threadIdx.x >> 5] = acc;
    __syncthreads();

    if (threadIdx.x == 0) {
        float s = 0.0f;
        #pragma unroll
        for (int i = 0; i < WPB; i++) s += sm[i];
        g_partial[blockIdx.x] = s;               // fixed slot per block
        __threadfence();                         // publish before ticket
        amLast = (atomicAdd(&g_count, 1u) == BLOCKS - 1);
    }
    __syncthreads();

    // Last-arriving CTA sums partials in FIXED index order -> deterministic.
    if (amLast) {
        float s = 0.0f;
        for (int i = threadIdx.x; i < BLOCKS; i += THREADS) s += g_partial[i];
        #pragma unroll
        for (int o = 16; o; o >>= 1) s += __shfl_xor_sync(0xffffffffu, s, o);
        __shared__ float sm2[WPB];
        if (lane == 0) sm2[threadIdx.x >> 5] = s;
        __syncthreads();
        if (threadIdx.x == 0) {
            float tot = 0.0f;
            #pragma unroll
            for (int i = 0; i < WPB; i++) tot += sm2[i];
            out[0] = -tot / (float)nrows;
            g_count = 0;                         // reset for next replay
        }
    }
}

extern "C" void kernel_launch(void* const* d_in, const int* in_sizes, int n_in,
                              void* d_out, int out_size) {
    const float4* logits = (const float4*)d_in[0];
    const float4* target = (const float4*)d_in[1];
    const int nrows = in_sizes[0] / 32;
    bce_fused<<<BLOCKS, THREADS>>>(logits, target, (float*)d_out, nrows);
}

// round 12
// speedup vs baseline: 1.5447x; 1.1230x over previous
#include <cuda_runtime.h>

// MySoftBCELoss: per-row soft BCE with argmax-label branch, mean-reduced.
// B = 1048576 rows, C = 32 cols, fp32. 256 MB streamed -> HBM-bound target.
//
// R10 ncu (float4, unroll4): 59.9us, DRAM 58.6%, occ 62.5%, issue 56.7%,
// regs 40 => still latency-exposed: ptxas did not front-batch the unrolled
// loads (reg budget), so each iter's EX2/LG2/REDUX chain drains the mem pipe.
// R11: explicit depth-1 software pipeline (next iter's 2x LDG.128 issued
// before current iter's compute; guaranteed-valid prefetch index, no branch)
// + register diet (running strict-> max tracker instead of 4-wide arrays;
// strict > keeps the FIRST max element => first-index tie-break preserved).

static constexpr int BLOCKS  = 2048;
static constexpr int THREADS = 256;
static constexpr int WPB     = THREADS / 32;

__device__ float        g_partial[BLOCKS];
__device__ unsigned int g_count = 0;   // reset by last block -> graph-replay safe

__global__ __launch_bounds__(THREADS) void bce_fused(const float4* __restrict__ lg4,
                                                     const float4* __restrict__ tg4,
                                                     float* __restrict__ out,
                                                     int nrows) {
    // log(1e-7), log(1-1e-7): clamping logs == clamping pred (log monotone).
    constexpr float LOGEPS   = -16.118095651f;
    constexpr float LOG1MEPS = -1.0000001192e-7f;

    const int lane    = threadIdx.x & 31;
    const int segbase = lane & 24;                  // (lane/8)*8: segment leader lane
    const unsigned segmask = 0xFFu << segbase;      // 8 lanes == one 32-col row

    const int n4     = nrows * 8;                   // float4s per tensor (32 cols / 4)
    const int stride = BLOCKS * THREADS;
    const int base   = blockIdx.x * THREADS + threadIdx.x;
    const int iters  = n4 / stride;                 // 16 for the bench shape (exact)

    float acc = 0.0f;

    if (iters > 0) {
        // Prime the pipeline.
        float4 xv = __ldcs(&lg4[base]);
        float4 tv = __ldcs(&tg4[base]);

        #pragma unroll 2
        for (int k = 0; k < iters; k++) {
            // Prefetch iter k+1 BEFORE computing iter k. Index is clamped to a
            // valid address (SEL, no branch) so the loads are unconditional and
            // always in flight during the compute below.
            const int inext = base + (k + 1 < iters ? (k + 1) * stride : 0);
            const float4 xv_n = __ldcs(&lg4[inext]);
            const float4 tv_n = __ldcs(&tg4[inext]);

            const float xs[4] = {xv.x, xv.y, xv.z, xv.w};
            const float ts[4] = {tv.x, tv.y, tv.z, tv.w};

            // Running trackers (register diet vs 4-wide arrays):
            unsigned bestb = 0;          // max target bits among this lane's 4 cols
            float    bestpr = 0.0f;      // t*logp of that element (first max kept)
            unsigned tb0 = 0;            // target bits of elem 0 (for label0 test)
            float    lmp0 = 0.0f;        // log1mp of elem 0 (for loss1 leader term)
            float    bce = 0.0f;         // this lane's share of the loss0 sum

            #pragma unroll
            for (int j = 0; j < 4; j++) {
                // log(pred) = -log(1+e^{-x}); log(1-pred) = -x - log(1+e^{-x})
                // 1 EX2 + 1 LG2 per element (MUFU-minimal).
                const float t  = ts[j];
                const float xc = fmaxf(xs[j], -80.0f);   // exp finite; inside eps-clamp
                const float e  = __expf(-xc);
                const float ld = __logf(1.0f + e);
                const float lp  = fminf(fmaxf(-ld,      LOGEPS), LOG1MEPS);
                const float lmp = fminf(fmaxf(-xc - ld, LOGEPS), LOG1MEPS);
                const float pr  = t * lp;
                const unsigned tb = __float_as_uint(t);  // t in [0,1): uint order == float

                bce += pr + (1.0f - t) * lmp;
                if (j == 0) { tb0 = tb; lmp0 = lmp; }
                if (tb > bestb) { bestb = tb; bestpr = pr; }   // strict >: first max kept
            }

            // Segmented argmax over the 32 columns of this lane's row.
            const unsigned segmax = __reduce_max_sync(segmask, bestb);
            const unsigned ball   = __ballot_sync(0xffffffffu, bestb == segmax) & segmask;
            const int firstlane   = __ffs(ball) - 1;   // first (lowest-column) max lane
            // argmax == 0 iff column 0 (lane segbase, elem 0) equals the max.
            const unsigned b0ball = __ballot_sync(0xffffffffu, tb0 == segmax);
            const bool label0     = (b0ball >> segbase) & 1u;

            // loss1: first-max lane adds t[lab]*logp[lab]; segment leader adds
            // log1mp[col 0].
            const float s1 = ((lane == firstlane) ? bestpr : 0.0f)
                           + ((lane == segbase)   ? lmp0   : 0.0f);

            acc += label0 ? (bce * (1.0f / 32.0f)) : s1;   // FSEL, no branch

            xv = xv_n; tv = tv_n;   // rotate pipeline
        }
    }

    // Shape-robust tail (no-op for the bench shape: 2^23 % 2^19 == 0).
    {
        const int i = base + iters * stride;
        if (i < n4) {
            const float4 xv = __ldcs(&lg4[i]);
            const float4 tv = __ldcs(&tg4[i]);
            const float xs[4] = {xv.x, xv.y, xv.z, xv.w};
            const float ts[4] = {tv.x, tv.y, tv.z, tv.w};
            unsigned bestb = 0; float bestpr = 0.0f;
            unsigned tb0 = 0; float lmp0 = 0.0f; float bce = 0.0f;
            #pragma unroll
            for (int j = 0; j < 4; j++) {
                const float t  = ts[j];
                const float xc = fmaxf(xs[j], -80.0f);
                const float e  = __expf(-xc);
                const float ld = __logf(1.0f + e);
                const float lp  = fminf(fmaxf(-ld,      LOGEPS), LOG1MEPS);
                const float lmp = fminf(fmaxf(-xc - ld, LOGEPS), LOG1MEPS);
                const float pr  = t * lp;
                const unsigned tb = __float_as_uint(t);
                bce += pr + (1.0f - t) * lmp;
                if (j == 0) { tb0 = tb; lmp0 = lmp; }
                if (tb > bestb) { bestb = tb; bestpr = pr; }
            }
            const unsigned segmax = __reduce_max_sync(segmask, bestb);
            const unsigned ball   = __ballot_sync(0xffffffffu, bestb == segmax) & segmask;
            const int firstlane   = __ffs(ball) - 1;
            const unsigned b0ball = __ballot_sync(0xffffffffu, tb0 == segmax);
            const bool label0     = (b0ball >> segbase) & 1u;
            const float s1 = ((lane == firstlane) ? bestpr : 0.0f)
                           + ((lane == segbase)   ? lmp0   : 0.0f);
            acc += label0 ? (bce * (1.0f / 32.0f)) : s1;
        }
    }

    // One warp reduction per warp, then fixed-order block sum.
    #pragma unroll
    for (int o = 16; o; o >>= 1) acc += __shfl_xor_sync(0xffffffffu, acc, o);

    __shared__ float sm[WPB];
    __shared__ bool  amLast;
    if (lane == 0) sm[threadIdx.x >> 5] = acc;
    __syncthreads();

    if (threadIdx.x == 0) {
        float s = 0.0f;
        #pragma unroll
        for (int i = 0; i < WPB; i++) s += sm[i];
        g_partial[blockIdx.x] = s;               // fixed slot per block
        __threadfence();                         // publish before ticket
        amLast = (atomicAdd(&g_count, 1u) == BLOCKS - 1);
    }
    __syncthreads();

    // Last-arriving CTA sums partials in FIXED index order -> deterministic.
    if (amLast) {
        float s = 0.0f;
        for (int i = threadIdx.x; i < BLOCKS; i += THREADS) s += g_partial[i];
        #pragma unroll
        for (int o = 16; o; o >>= 1) s += __shfl_xor_sync(0xffffffffu, s, o);
        __shared__ float sm2[WPB];
        if (lane == 0) sm2[threadIdx.x >> 5] = s;
        __syncthreads();
        if (threadIdx.x == 0) {
            float tot = 0.0f;
            #pragma unroll
            for (int i = 0; i < WPB; i++) tot += sm2[i];
            out[0] = -tot / (float)nrows;
            g_count = 0;                         // reset for next replay
        }
    }
}

extern "C" void kernel_launch(void* const* d_in, const int* in_sizes, int n_in,
                              void* d_out, int out_size) {
    const float4* logits = (const float4*)d_in[0];
    const float4* target = (const float4*)d_in[1];
    const int nrows = in_sizes[0] / 32;
    bce_fused<<<BLOCKS, THREADS>>>(logits, target, (float*)d_out, nrows);
}